// round 2
// baseline (speedup 1.0000x reference)
#include <cuda_runtime.h>
#include <math.h>

#define D_MODEL 1024
#define N_HEADS 16
#define D_HEAD  64
#define BATCH   4
#define SEQ     2048
#define M_TOK   (BATCH * SEQ)     // 8192
#define QKV_N   (3 * D_MODEL)     // 3072

// Scratch (device globals; no allocation allowed anywhere).
// Referenced directly from device code — host never needs their address,
// so kernel_launch is pure kernel launches (strictly graph-capturable).
__device__ float g_qkv[(size_t)M_TOK * QKV_N];    // 96 MB: [token][{q,k,v} x h x d]
__device__ float g_att[(size_t)M_TOK * D_MODEL];  // 32 MB: attention out [token][h*64+d]

// ---------------------------------------------------------------------------
// fp32 SGEMM body: C[M,N] = A[M,K] @ B[K,N], row-major.
// 128x128 block tile, BK=16, 256 threads, 8x8 per-thread micro-tile.
// ---------------------------------------------------------------------------
template <int BM, int BN, int BK, int TM, int TN>
__device__ __forceinline__ void sgemm_body(
    const float* __restrict__ A, const float* __restrict__ B,
    float* __restrict__ C, int M, int N, int K)
{
    __shared__ float As[BK][BM];   // A tile stored transposed
    __shared__ float Bs[BK][BN];

    const int tid  = threadIdx.x;
    const int cRow = blockIdx.y;
    const int cCol = blockIdx.x;

    const int tRow = (tid / (BN / TN)) * TM;   // 0..120
    const int tCol = (tid % (BN / TN)) * TN;   // 0..120

    A += (size_t)cRow * BM * K;
    B += (size_t)cCol * BN;
    C += (size_t)cRow * BM * N + cCol * BN;

    const int aRow = tid / (BK / 4);           // 0..63
    const int aCol = (tid % (BK / 4)) * 4;     // 0,4,8,12
    const int bRow = tid / (BN / 4);           // 0..7
    const int bCol = (tid % (BN / 4)) * 4;     // 0..124

    float acc[TM][TN] = {};
    float regM[TM], regN[TN];

    for (int k0 = 0; k0 < K; k0 += BK) {
        #pragma unroll
        for (int r = 0; r < BM; r += 64) {
            float4 v = *(const float4*)(&A[(size_t)(aRow + r) * K + k0 + aCol]);
            As[aCol + 0][aRow + r] = v.x;
            As[aCol + 1][aRow + r] = v.y;
            As[aCol + 2][aRow + r] = v.z;
            As[aCol + 3][aRow + r] = v.w;
        }
        #pragma unroll
        for (int r = 0; r < BK; r += 8) {
            *(float4*)(&Bs[bRow + r][bCol]) =
                *(const float4*)(&B[(size_t)(k0 + bRow + r) * N + bCol]);
        }
        __syncthreads();

        #pragma unroll
        for (int kk = 0; kk < BK; kk++) {
            #pragma unroll
            for (int i = 0; i < TM; i++) regM[i] = As[kk][tRow + i];
            #pragma unroll
            for (int j = 0; j < TN; j++) regN[j] = Bs[kk][tCol + j];
            #pragma unroll
            for (int i = 0; i < TM; i++)
                #pragma unroll
                for (int j = 0; j < TN; j++)
                    acc[i][j] += regM[i] * regN[j];
        }
        __syncthreads();
    }

    #pragma unroll
    for (int i = 0; i < TM; i++)
        #pragma unroll
        for (int j = 0; j < TN; j += 4) {
            float4 v = {acc[i][j], acc[i][j + 1], acc[i][j + 2], acc[i][j + 3]};
            *(float4*)(&C[(size_t)(tRow + i) * N + tCol + j]) = v;
        }
}

// Specialized wrappers (globals referenced in device code only)
__global__ __launch_bounds__(256, 2) void qkv_gemm_kernel(
    const float* __restrict__ x, const float* __restrict__ W_qkv)
{
    sgemm_body<128, 128, 16, 8, 8>(x, W_qkv, g_qkv, M_TOK, QKV_N, D_MODEL);
}

__global__ __launch_bounds__(256, 2) void out_gemm_kernel(
    const float* __restrict__ W_out, float* __restrict__ out)
{
    sgemm_body<128, 128, 16, 8, 8>(g_att, W_out, out, M_TOK, D_MODEL, D_MODEL);
}

// ---------------------------------------------------------------------------
// Causal flash attention, fp32, one thread per query row.
// CTA: 128 threads = 128 query rows. K/V tiles (32x64) staged in smem;
// all smem reads are warp-uniform broadcasts (conflict-free).
// ---------------------------------------------------------------------------
#define BQ   128
#define BKT  32

__global__ __launch_bounds__(128) void attn_kernel()
{
    const int qTile = blockIdx.x;          // 0..15
    const int h     = blockIdx.y;          // 0..15
    const int b     = blockIdx.z;          // 0..3
    const int tid   = threadIdx.x;
    const int qRow  = qTile * BQ + tid;    // 0..2047
    const size_t rowBase = ((size_t)b * SEQ + qRow) * QKV_N;
    const int hOff = h * D_HEAD;

    __shared__ float Ks[BKT][D_HEAD];
    __shared__ float Vs[BKT][D_HEAD];

    float q[D_HEAD], o[D_HEAD];
    #pragma unroll
    for (int d = 0; d < D_HEAD; d += 4) {
        float4 v = *(const float4*)&g_qkv[rowBase + hOff + d];
        q[d] = v.x; q[d + 1] = v.y; q[d + 2] = v.z; q[d + 3] = v.w;
    }
    #pragma unroll
    for (int d = 0; d < D_HEAD; d++) o[d] = 0.f;

    float m = -INFINITY, l = 0.f;
    const float scale = 0.125f;            // 1/sqrt(64)

    const int kEnd = qTile * BQ + BQ;      // causal limit (exclusive)
    for (int kBase = 0; kBase < kEnd; kBase += BKT) {
        __syncthreads();                   // previous-tile reads done
        #pragma unroll
        for (int r = 0; r < BKT; r += 8) {
            int row = r + (tid >> 4);
            int col = (tid & 15) * 4;
            size_t src = ((size_t)b * SEQ + kBase + row) * QKV_N + hOff + col;
            *(float4*)&Ks[row][col] = *(const float4*)&g_qkv[src + D_MODEL];
            *(float4*)&Vs[row][col] = *(const float4*)&g_qkv[src + 2 * D_MODEL];
        }
        __syncthreads();

        float s[BKT];
        #pragma unroll
        for (int j = 0; j < BKT; j++) {
            float acc = 0.f;
            #pragma unroll
            for (int d = 0; d < D_HEAD; d++) acc += q[d] * Ks[j][d];
            s[j] = (kBase + j <= qRow) ? acc * scale : -INFINITY;
        }

        float mt = m;
        #pragma unroll
        for (int j = 0; j < BKT; j++) mt = fmaxf(mt, s[j]);
        float corr = __expf(m - mt);
        float ps = 0.f;
        #pragma unroll
        for (int j = 0; j < BKT; j++) { s[j] = __expf(s[j] - mt); ps += s[j]; }
        l = l * corr + ps;
        m = mt;

        #pragma unroll
        for (int d = 0; d < D_HEAD; d++) o[d] *= corr;
        #pragma unroll
        for (int j = 0; j < BKT; j++) {
            float p = s[j];
            #pragma unroll
            for (int d = 0; d < D_HEAD; d++) o[d] += p * Vs[j][d];
        }
    }

    const float inv = 1.f / l;
    const size_t outBase = ((size_t)b * SEQ + qRow) * D_MODEL + hOff;
    #pragma unroll
    for (int d = 0; d < D_HEAD; d += 4) {
        float4 v = {o[d] * inv, o[d + 1] * inv, o[d + 2] * inv, o[d + 3] * inv};
        *(float4*)&g_att[outBase + d] = v;
    }
}

// ---------------------------------------------------------------------------
extern "C" void kernel_launch(void* const* d_in, const int* in_sizes, int n_in,
                              void* d_out, int out_size)
{
    const float* x     = (const float*)d_in[0];   // [4,2048,1024]
    const float* W_qkv = (const float*)d_in[1];   // [1024,3072]
    const float* W_out = (const float*)d_in[2];   // [1024,1024]
    // d_in[3] = mask (causal tril), applied analytically
    float* out = (float*)d_out;

    // 1) QKV projection: [8192,1024] @ [1024,3072] -> g_qkv
    {
        dim3 grid(QKV_N / 128, M_TOK / 128);
        qkv_gemm_kernel<<<grid, 256>>>(x, W_qkv);
    }
    // 2) Causal flash attention per (b, h, q-tile): g_qkv -> g_att
    {
        dim3 grid(SEQ / BQ, N_HEADS, BATCH);
        attn_kernel<<<grid, 128>>>();
    }
    // 3) Output projection: g_att @ W_out -> out
    {
        dim3 grid(D_MODEL / 128, M_TOK / 128);
        out_gemm_kernel<<<grid, 256>>>(W_out, out);
    }
}

// round 4
// speedup vs baseline: 1.3576x; 1.3576x over previous
#include <cuda_runtime.h>
#include <cuda_bf16.h>
#include <math.h>
#include <stdint.h>

#define D_MODEL 1024
#define N_HEADS 16
#define D_HEAD  64
#define BATCH   4
#define SEQ     2048
#define M_TOK   (BATCH * SEQ)     // 8192
#define QKV_N   (3 * D_MODEL)     // 3072
#define GK      1024              // GEMM K (= D_MODEL)

// ---------------------------------------------------------------------------
// Device-global scratch (no allocations allowed anywhere).
// ---------------------------------------------------------------------------
__device__ float         g_qkv[(size_t)M_TOK * QKV_N];        // 96 MB fp32 qkv
__device__ __nv_bfloat16 g_xhi[(size_t)M_TOK * D_MODEL];
__device__ __nv_bfloat16 g_xlo[(size_t)M_TOK * D_MODEL];
__device__ __nv_bfloat16 g_wqkvT_hi[(size_t)QKV_N * D_MODEL]; // W^T [N][K]
__device__ __nv_bfloat16 g_wqkvT_lo[(size_t)QKV_N * D_MODEL];
__device__ __nv_bfloat16 g_woutT_hi[(size_t)D_MODEL * D_MODEL];
__device__ __nv_bfloat16 g_woutT_lo[(size_t)D_MODEL * D_MODEL];
__device__ __nv_bfloat16 g_atthi[(size_t)M_TOK * D_MODEL];
__device__ __nv_bfloat16 g_attlo[(size_t)M_TOK * D_MODEL];

// ---------------------------------------------------------------------------
// Baseline-PTX helpers (no tcgen05: harness targets compute_103, not 103a)
// ---------------------------------------------------------------------------
__device__ __forceinline__ uint32_t smem_u32(const void* p) {
    uint32_t a;
    asm("{ .reg .u64 t; cvta.to.shared.u64 t, %1; cvt.u32.u64 %0, t; }"
        : "=r"(a) : "l"(p));
    return a;
}
__device__ __forceinline__ void cp16(uint32_t dst, const void* src) {
    asm volatile("cp.async.cg.shared.global [%0], [%1], 16;"
                 :: "r"(dst), "l"(src) : "memory");
}
#define CP_COMMIT() asm volatile("cp.async.commit_group;" ::: "memory")
#define CP_WAIT(n)  asm volatile("cp.async.wait_group %0;" :: "n"(n) : "memory")

__device__ __forceinline__ void ldsm_x4(uint32_t* r, uint32_t addr) {
    asm volatile("ldmatrix.sync.aligned.m8n8.x4.shared.b16 {%0,%1,%2,%3}, [%4];"
                 : "=r"(r[0]), "=r"(r[1]), "=r"(r[2]), "=r"(r[3]) : "r"(addr));
}
__device__ __forceinline__ void mma_bf16(float* d, const uint32_t* a, const uint32_t* b) {
    asm volatile(
        "mma.sync.aligned.m16n8k16.row.col.f32.bf16.bf16.f32 "
        "{%0,%1,%2,%3}, {%4,%5,%6,%7}, {%8,%9}, {%0,%1,%2,%3};"
        : "+f"(d[0]), "+f"(d[1]), "+f"(d[2]), "+f"(d[3])
        : "r"(a[0]), "r"(a[1]), "r"(a[2]), "r"(a[3]), "r"(b[0]), "r"(b[1]));
}
#define SWZ128(o) ((o) ^ (((o) >> 3) & 0x70))

// ---------------------------------------------------------------------------
// Prep kernels
// ---------------------------------------------------------------------------
__global__ void split_x_kernel(const float* __restrict__ x) {
    size_t i = ((size_t)blockIdx.x * blockDim.x + threadIdx.x) * 4;
    if (i >= (size_t)M_TOK * D_MODEL) return;
    float4 v = *(const float4*)(x + i);
    __nv_bfloat16 h0 = __float2bfloat16(v.x), h1 = __float2bfloat16(v.y);
    __nv_bfloat16 h2 = __float2bfloat16(v.z), h3 = __float2bfloat16(v.w);
    __nv_bfloat162* hp = (__nv_bfloat162*)(g_xhi + i);
    __nv_bfloat162* lp = (__nv_bfloat162*)(g_xlo + i);
    hp[0] = __nv_bfloat162(h0, h1);
    hp[1] = __nv_bfloat162(h2, h3);
    lp[0] = __nv_bfloat162(__float2bfloat16(v.x - __bfloat162float(h0)),
                           __float2bfloat16(v.y - __bfloat162float(h1)));
    lp[1] = __nv_bfloat162(__float2bfloat16(v.z - __bfloat162float(h2)),
                           __float2bfloat16(v.w - __bfloat162float(h3)));
}

// W [K][N] -> T_hi/lo [N][K]
__device__ __forceinline__ void transpose_split_body(
    const float* __restrict__ W, __nv_bfloat16* __restrict__ Thi,
    __nv_bfloat16* __restrict__ Tlo, int K, int N)
{
    __shared__ float t[32][33];
    int tx = threadIdx.x, ty = threadIdx.y;
    int x = blockIdx.x * 32 + tx;
    int y0 = blockIdx.y * 32;
    #pragma unroll
    for (int j = 0; j < 32; j += 8)
        t[ty + j][tx] = W[(size_t)(y0 + ty + j) * N + x];
    __syncthreads();
    int xo = y0 + tx;
    int yo = blockIdx.x * 32;
    #pragma unroll
    for (int j = 0; j < 32; j += 8) {
        float v = t[tx][ty + j];
        __nv_bfloat16 h = __float2bfloat16(v);
        size_t o = (size_t)(yo + ty + j) * K + xo;
        Thi[o] = h;
        Tlo[o] = __float2bfloat16(v - __bfloat162float(h));
    }
}
__global__ void tr_wqkv_kernel(const float* __restrict__ W) {
    transpose_split_body(W, g_wqkvT_hi, g_wqkvT_lo, D_MODEL, QKV_N);
}
__global__ void tr_wout_kernel(const float* __restrict__ W) {
    transpose_split_body(W, g_woutT_hi, g_woutT_lo, D_MODEL, D_MODEL);
}

// ---------------------------------------------------------------------------
// Split-bf16 GEMM via mma.sync: C[M,Ntot] = A@B^T, A hi/lo [M][1024] (k-major),
// B hi/lo [Ntot][1024] (k-major). CTA 128x128, KC=64, 2-stage cp.async pipe.
// 256 threads = 8 warps; warp tile 32(M)x64(N); m16n8k16 bf16 mma, 3-term split.
// ---------------------------------------------------------------------------
#define KC      64
#define TILE_B  (128 * 128)          // 16KB: 128 rows x (64 bf16 = 128B)
#define STAGE_B (4 * TILE_B)         // Ahi,Alo,Bhi,Blo
#define NSTEPS  (GK / KC)            // 16

// Load one 128x64-bf16 tile (k0 elem offset in global k) into swizzled smem.
__device__ __forceinline__ void tile_loads(
    uint32_t sbase, const __nv_bfloat16* __restrict__ g, int k0, int tid)
{
    #pragma unroll
    for (int j = 0; j < 4; j++) {
        int i = tid + j * 256;            // 0..1023 chunk id
        int r = i >> 3, c = i & 7;        // row, 16B chunk
        cp16(sbase + SWZ128(r * 128 + c * 16), g + (size_t)r * GK + k0 + c * 8);
    }
}

__device__ __forceinline__ void gemm_body(
    const __nv_bfloat16* __restrict__ Ahi, const __nv_bfloat16* __restrict__ Alo,
    const __nv_bfloat16* __restrict__ Bhi, const __nv_bfloat16* __restrict__ Blo,
    float* __restrict__ C, int Ntot)
{
    extern __shared__ char gsm[];
    const int tid  = threadIdx.x;
    const int wid  = tid >> 5, lane = tid & 31;
    const int cN   = blockIdx.x, cM = blockIdx.y;
    const int wm   = (wid & 3) * 32;          // warp M offset in tile
    const int wn   = (wid >> 2) * 64;         // warp N offset in tile

    const __nv_bfloat16* gAh = Ahi + (size_t)cM * 128 * GK;
    const __nv_bfloat16* gAl = Alo + (size_t)cM * 128 * GK;
    const __nv_bfloat16* gBh = Bhi + (size_t)cN * 128 * GK;
    const __nv_bfloat16* gBl = Blo + (size_t)cN * 128 * GK;

    const uint32_t smbase = smem_u32(gsm);

    float acc[2][8][4];
    #pragma unroll
    for (int mi = 0; mi < 2; mi++)
        #pragma unroll
        for (int nf = 0; nf < 8; nf++)
            #pragma unroll
            for (int e = 0; e < 4; e++) acc[mi][nf][e] = 0.f;

    // ldmatrix logical offsets (pre-swizzle), within a tile:
    // A: row = wm + mi*16 + (lane&15), bytes_k = kk*32 + (lane>>4)*16
    const int aRow = wm + (lane & 15);
    const int aKof = (lane >> 4) * 16;
    // B: row(n) = wn + g*16 + ((lane>>4)<<3) + (lane&7), bytes_k = kk*32 + ((lane>>3)&1)*16
    const int bRow = wn + ((lane >> 4) << 3) + (lane & 7);
    const int bKof = ((lane >> 3) & 1) * 16;

    // prologue: stage 0
    {
        uint32_t st = smbase;
        tile_loads(st + 0 * TILE_B, gAh, 0, tid);
        tile_loads(st + 1 * TILE_B, gAl, 0, tid);
        tile_loads(st + 2 * TILE_B, gBh, 0, tid);
        tile_loads(st + 3 * TILE_B, gBl, 0, tid);
        CP_COMMIT();
    }

    for (int kc = 0; kc < NSTEPS; kc++) {
        if (kc + 1 < NSTEPS) {
            uint32_t st = smbase + ((kc + 1) & 1) * STAGE_B;
            int k0 = (kc + 1) * KC;
            tile_loads(st + 0 * TILE_B, gAh, k0, tid);
            tile_loads(st + 1 * TILE_B, gAl, k0, tid);
            tile_loads(st + 2 * TILE_B, gBh, k0, tid);
            tile_loads(st + 3 * TILE_B, gBl, k0, tid);
            CP_COMMIT();
            CP_WAIT(1);
        } else {
            CP_WAIT(0);
        }
        __syncthreads();

        const uint32_t sAh = smbase + (kc & 1) * STAGE_B;
        const uint32_t sAl = sAh + TILE_B;
        const uint32_t sBh = sAh + 2 * TILE_B;
        const uint32_t sBl = sAh + 3 * TILE_B;

        #pragma unroll
        for (int kk = 0; kk < 4; kk++) {          // 4 x k16 within KC=64
            const int kb = kk * 32;
            uint32_t aH[2][4], aL[2][4], bH[4][4], bL[4][4];
            #pragma unroll
            for (int mi = 0; mi < 2; mi++) {
                uint32_t off = SWZ128((aRow + mi * 16) * 128 + kb + aKof);
                ldsm_x4(aH[mi], sAh + off);
                ldsm_x4(aL[mi], sAl + off);
            }
            #pragma unroll
            for (int g = 0; g < 4; g++) {
                uint32_t off = SWZ128((bRow + g * 16) * 128 + kb + bKof);
                ldsm_x4(bH[g], sBh + off);
                ldsm_x4(bL[g], sBl + off);
            }
            #pragma unroll
            for (int mi = 0; mi < 2; mi++)
                #pragma unroll
                for (int nf = 0; nf < 8; nf++) {
                    const uint32_t* bh = &bH[nf >> 1][(nf & 1) * 2];
                    const uint32_t* bl = &bL[nf >> 1][(nf & 1) * 2];
                    mma_bf16(acc[mi][nf], aH[mi], bh);   // hi*hi
                    mma_bf16(acc[mi][nf], aH[mi], bl);   // hi*lo
                    mma_bf16(acc[mi][nf], aL[mi], bh);   // lo*hi
                }
        }
        __syncthreads();
    }

    // Epilogue
    const int row0 = cM * 128 + wm + (lane >> 2);
    const int col0 = cN * 128 + wn + (lane & 3) * 2;
    #pragma unroll
    for (int mi = 0; mi < 2; mi++)
        #pragma unroll
        for (int nf = 0; nf < 8; nf++) {
            float* c0 = C + (size_t)(row0 + mi * 16) * Ntot + col0 + nf * 8;
            float* c1 = c0 + 8 * Ntot;
            *(float2*)c0 = make_float2(acc[mi][nf][0], acc[mi][nf][1]);
            *(float2*)c1 = make_float2(acc[mi][nf][2], acc[mi][nf][3]);
        }
}

__global__ __launch_bounds__(256, 1) void qkv_gemm2_kernel() {
    gemm_body(g_xhi, g_xlo, g_wqkvT_hi, g_wqkvT_lo, g_qkv, QKV_N);
}
__global__ __launch_bounds__(256, 1) void out_gemm2_kernel(float* __restrict__ out) {
    gemm_body(g_atthi, g_attlo, g_woutT_hi, g_woutT_lo, out, D_MODEL);
}

// ---------------------------------------------------------------------------
// Causal flash attention, fp32, one thread per query row (unchanged core).
// ---------------------------------------------------------------------------
#define BQ   128
#define BKT  32

__global__ __launch_bounds__(128) void attn_kernel()
{
    const int qTile = blockIdx.x;
    const int h     = blockIdx.y;
    const int b     = blockIdx.z;
    const int tid   = threadIdx.x;
    const int qRow  = qTile * BQ + tid;
    const size_t rowBase = ((size_t)b * SEQ + qRow) * QKV_N;
    const int hOff = h * D_HEAD;

    __shared__ float Ks[BKT][D_HEAD];
    __shared__ float Vs[BKT][D_HEAD];

    float q[D_HEAD], o[D_HEAD];
    #pragma unroll
    for (int d = 0; d < D_HEAD; d += 4) {
        float4 v = *(const float4*)&g_qkv[rowBase + hOff + d];
        q[d] = v.x; q[d + 1] = v.y; q[d + 2] = v.z; q[d + 3] = v.w;
    }
    #pragma unroll
    for (int d = 0; d < D_HEAD; d++) o[d] = 0.f;

    float m = -INFINITY, l = 0.f;
    const float scale = 0.125f;

    const int kEnd = qTile * BQ + BQ;
    for (int kBase = 0; kBase < kEnd; kBase += BKT) {
        __syncthreads();
        #pragma unroll
        for (int r = 0; r < BKT; r += 8) {
            int row = r + (tid >> 4);
            int col = (tid & 15) * 4;
            size_t src = ((size_t)b * SEQ + kBase + row) * QKV_N + hOff + col;
            *(float4*)&Ks[row][col] = *(const float4*)&g_qkv[src + D_MODEL];
            *(float4*)&Vs[row][col] = *(const float4*)&g_qkv[src + 2 * D_MODEL];
        }
        __syncthreads();

        float s[BKT];
        #pragma unroll
        for (int j = 0; j < BKT; j++) {
            float acc = 0.f;
            #pragma unroll
            for (int d = 0; d < D_HEAD; d++) acc += q[d] * Ks[j][d];
            s[j] = (kBase + j <= qRow) ? acc * scale : -INFINITY;
        }

        float mt = m;
        #pragma unroll
        for (int j = 0; j < BKT; j++) mt = fmaxf(mt, s[j]);
        float corr = __expf(m - mt);
        float ps = 0.f;
        #pragma unroll
        for (int j = 0; j < BKT; j++) { s[j] = __expf(s[j] - mt); ps += s[j]; }
        l = l * corr + ps;
        m = mt;

        #pragma unroll
        for (int d = 0; d < D_HEAD; d++) o[d] *= corr;
        #pragma unroll
        for (int j = 0; j < BKT; j++) {
            float p = s[j];
            #pragma unroll
            for (int d = 0; d < D_HEAD; d++) o[d] += p * Vs[j][d];
        }
    }

    const float inv = 1.f / l;
    const size_t outBase = ((size_t)b * SEQ + qRow) * D_MODEL + hOff;
    #pragma unroll
    for (int d = 0; d < D_HEAD; d += 2) {
        float v0 = o[d] * inv, v1 = o[d + 1] * inv;
        __nv_bfloat16 h0 = __float2bfloat16(v0), h1 = __float2bfloat16(v1);
        *(__nv_bfloat162*)&g_atthi[outBase + d] = __nv_bfloat162(h0, h1);
        *(__nv_bfloat162*)&g_attlo[outBase + d] =
            __nv_bfloat162(__float2bfloat16(v0 - __bfloat162float(h0)),
                           __float2bfloat16(v1 - __bfloat162float(h1)));
    }
}

// ---------------------------------------------------------------------------
extern "C" void kernel_launch(void* const* d_in, const int* in_sizes, int n_in,
                              void* d_out, int out_size)
{
    const float* x     = (const float*)d_in[0];
    const float* W_qkv = (const float*)d_in[1];
    const float* W_out = (const float*)d_in[2];
    float* out = (float*)d_out;

    const int dyn_smem = 2 * STAGE_B;   // 128 KB
    cudaFuncSetAttribute(qkv_gemm2_kernel,
                         cudaFuncAttributeMaxDynamicSharedMemorySize, dyn_smem);
    cudaFuncSetAttribute(out_gemm2_kernel,
                         cudaFuncAttributeMaxDynamicSharedMemorySize, dyn_smem);

    // 0) Input split / weight transposes
    {
        size_t n4 = (size_t)M_TOK * D_MODEL / 4;
        split_x_kernel<<<(unsigned)((n4 + 255) / 256), 256>>>(x);
        dim3 blk(32, 8);
        tr_wqkv_kernel<<<dim3(QKV_N / 32, D_MODEL / 32), blk>>>(W_qkv);
        tr_wout_kernel<<<dim3(D_MODEL / 32, D_MODEL / 32), blk>>>(W_out);
    }
    // 1) QKV projection: g_x{hi,lo} @ W_qkv^T-tiles -> g_qkv (fp32)
    qkv_gemm2_kernel<<<dim3(QKV_N / 128, M_TOK / 128), 256, dyn_smem>>>();
    // 2) Causal flash attention: g_qkv -> g_att{hi,lo}
    attn_kernel<<<dim3(SEQ / BQ, N_HEADS, BATCH), 128>>>();
    // 3) Output projection: g_att{hi,lo} @ W_out^T-tiles -> out
    out_gemm2_kernel<<<dim3(D_MODEL / 128, M_TOK / 128), 256, dyn_smem>>>(out);
}

// round 5
// speedup vs baseline: 4.1685x; 3.0706x over previous
#include <cuda_runtime.h>
#include <cuda_bf16.h>
#include <math.h>
#include <stdint.h>

#define D_MODEL 1024
#define N_HEADS 16
#define D_HEAD  64
#define BATCH   4
#define SEQ     2048
#define M_TOK   (BATCH * SEQ)     // 8192
#define QKV_N   (3 * D_MODEL)     // 3072
#define GK      1024
#define HB      (BATCH * N_HEADS) // 64

// ---------------------------------------------------------------------------
// Device-global scratch
// ---------------------------------------------------------------------------
__device__ __nv_bfloat16 g_xhi[(size_t)M_TOK * D_MODEL];
__device__ __nv_bfloat16 g_xlo[(size_t)M_TOK * D_MODEL];
__device__ __nv_bfloat16 g_wqkvT_hi[(size_t)QKV_N * D_MODEL];
__device__ __nv_bfloat16 g_wqkvT_lo[(size_t)QKV_N * D_MODEL];
__device__ __nv_bfloat16 g_woutT_hi[(size_t)D_MODEL * D_MODEL];
__device__ __nv_bfloat16 g_woutT_lo[(size_t)D_MODEL * D_MODEL];
// q/k/v split, head-contiguous: [(b*16+h)][t][64]
__device__ __nv_bfloat16 g_qhi[(size_t)HB * SEQ * D_HEAD];
__device__ __nv_bfloat16 g_qlo[(size_t)HB * SEQ * D_HEAD];
__device__ __nv_bfloat16 g_khi[(size_t)HB * SEQ * D_HEAD];
__device__ __nv_bfloat16 g_klo[(size_t)HB * SEQ * D_HEAD];
__device__ __nv_bfloat16 g_vhi[(size_t)HB * SEQ * D_HEAD];
__device__ __nv_bfloat16 g_vlo[(size_t)HB * SEQ * D_HEAD];
__device__ __nv_bfloat16 g_atthi[(size_t)M_TOK * D_MODEL];
__device__ __nv_bfloat16 g_attlo[(size_t)M_TOK * D_MODEL];

// ---------------------------------------------------------------------------
// Baseline-PTX helpers (compute_103 target: no tcgen05)
// ---------------------------------------------------------------------------
__device__ __forceinline__ uint32_t smem_u32(const void* p) {
    uint32_t a;
    asm("{ .reg .u64 t; cvta.to.shared.u64 t, %1; cvt.u32.u64 %0, t; }"
        : "=r"(a) : "l"(p));
    return a;
}
__device__ __forceinline__ void cp16(uint32_t dst, const void* src) {
    asm volatile("cp.async.cg.shared.global [%0], [%1], 16;"
                 :: "r"(dst), "l"(src) : "memory");
}
#define CP_COMMIT() asm volatile("cp.async.commit_group;" ::: "memory")
#define CP_WAIT(n)  asm volatile("cp.async.wait_group %0;" :: "n"(n) : "memory")

__device__ __forceinline__ void ldsm_x4(uint32_t* r, uint32_t addr) {
    asm volatile("ldmatrix.sync.aligned.m8n8.x4.shared.b16 {%0,%1,%2,%3}, [%4];"
                 : "=r"(r[0]), "=r"(r[1]), "=r"(r[2]), "=r"(r[3]) : "r"(addr));
}
__device__ __forceinline__ void ldsm_x4t(uint32_t* r, uint32_t addr) {
    asm volatile("ldmatrix.sync.aligned.m8n8.x4.trans.shared.b16 {%0,%1,%2,%3}, [%4];"
                 : "=r"(r[0]), "=r"(r[1]), "=r"(r[2]), "=r"(r[3]) : "r"(addr));
}
__device__ __forceinline__ void mma_bf16(float* d, const uint32_t* a, const uint32_t* b) {
    asm volatile(
        "mma.sync.aligned.m16n8k16.row.col.f32.bf16.bf16.f32 "
        "{%0,%1,%2,%3}, {%4,%5,%6,%7}, {%8,%9}, {%0,%1,%2,%3};"
        : "+f"(d[0]), "+f"(d[1]), "+f"(d[2]), "+f"(d[3])
        : "r"(a[0]), "r"(a[1]), "r"(a[2]), "r"(a[3]), "r"(b[0]), "r"(b[1]));
}
#define SWZ128(o) ((o) ^ (((o) >> 3) & 0x70))

__device__ __forceinline__ uint32_t pack_bf2(__nv_bfloat16 a, __nv_bfloat16 b) {
    __nv_bfloat162 t(a, b);
    return *(uint32_t*)&t;
}

// ---------------------------------------------------------------------------
// Prep kernels
// ---------------------------------------------------------------------------
__global__ void split_x_kernel(const float* __restrict__ x) {
    size_t i = ((size_t)blockIdx.x * blockDim.x + threadIdx.x) * 4;
    if (i >= (size_t)M_TOK * D_MODEL) return;
    float4 v = *(const float4*)(x + i);
    __nv_bfloat16 h0 = __float2bfloat16(v.x), h1 = __float2bfloat16(v.y);
    __nv_bfloat16 h2 = __float2bfloat16(v.z), h3 = __float2bfloat16(v.w);
    __nv_bfloat162* hp = (__nv_bfloat162*)(g_xhi + i);
    __nv_bfloat162* lp = (__nv_bfloat162*)(g_xlo + i);
    hp[0] = __nv_bfloat162(h0, h1);
    hp[1] = __nv_bfloat162(h2, h3);
    lp[0] = __nv_bfloat162(__float2bfloat16(v.x - __bfloat162float(h0)),
                           __float2bfloat16(v.y - __bfloat162float(h1)));
    lp[1] = __nv_bfloat162(__float2bfloat16(v.z - __bfloat162float(h2)),
                           __float2bfloat16(v.w - __bfloat162float(h3)));
}

__device__ __forceinline__ void transpose_split_body(
    const float* __restrict__ W, __nv_bfloat16* __restrict__ Thi,
    __nv_bfloat16* __restrict__ Tlo, int K, int N)
{
    __shared__ float t[32][33];
    int tx = threadIdx.x, ty = threadIdx.y;
    int x = blockIdx.x * 32 + tx;
    int y0 = blockIdx.y * 32;
    #pragma unroll
    for (int j = 0; j < 32; j += 8)
        t[ty + j][tx] = W[(size_t)(y0 + ty + j) * N + x];
    __syncthreads();
    int xo = y0 + tx;
    int yo = blockIdx.x * 32;
    #pragma unroll
    for (int j = 0; j < 32; j += 8) {
        float v = t[tx][ty + j];
        __nv_bfloat16 h = __float2bfloat16(v);
        size_t o = (size_t)(yo + ty + j) * K + xo;
        Thi[o] = h;
        Tlo[o] = __float2bfloat16(v - __bfloat162float(h));
    }
}
__global__ void tr_wqkv_kernel(const float* __restrict__ W) {
    transpose_split_body(W, g_wqkvT_hi, g_wqkvT_lo, D_MODEL, QKV_N);
}
__global__ void tr_wout_kernel(const float* __restrict__ W) {
    transpose_split_body(W, g_woutT_hi, g_woutT_lo, D_MODEL, D_MODEL);
}

// ---------------------------------------------------------------------------
// Split-bf16 GEMM (mma.sync). MODE 0: write fp32 C. MODE 1: split-write q/k/v.
// ---------------------------------------------------------------------------
#define KC      64
#define TILE_B  (128 * 128)
#define STAGE_B (4 * TILE_B)
#define NSTEPS  (GK / KC)

__device__ __forceinline__ void tile_loads(
    uint32_t sbase, const __nv_bfloat16* __restrict__ g, int k0, int tid)
{
    #pragma unroll
    for (int j = 0; j < 4; j++) {
        int i = tid + j * 256;
        int r = i >> 3, c = i & 7;
        cp16(sbase + SWZ128(r * 128 + c * 16), g + (size_t)r * GK + k0 + c * 8);
    }
}

__device__ __forceinline__ void write_qkv_pair(int row, int col, float v0, float v1) {
    int b = row >> 11, t = row & 2047;
    int which = col >> 10;
    int h = (col >> 6) & 15;
    int d = col & 63;
    if (which == 0) { v0 *= 0.125f; v1 *= 0.125f; }   // fold 1/sqrt(64) into q
    size_t off = (((size_t)((b << 4) + h) << 11) + (size_t)t) * D_HEAD + d;
    __nv_bfloat16 h0 = __float2bfloat16(v0), h1 = __float2bfloat16(v1);
    uint32_t hi = pack_bf2(h0, h1);
    uint32_t lo = pack_bf2(__float2bfloat16(v0 - __bfloat162float(h0)),
                           __float2bfloat16(v1 - __bfloat162float(h1)));
    __nv_bfloat16* dh = (which == 0) ? g_qhi : (which == 1) ? g_khi : g_vhi;
    __nv_bfloat16* dl = (which == 0) ? g_qlo : (which == 1) ? g_klo : g_vlo;
    *(uint32_t*)&dh[off] = hi;
    *(uint32_t*)&dl[off] = lo;
}

template <int MODE>
__device__ __forceinline__ void gemm_body(
    const __nv_bfloat16* __restrict__ Ahi, const __nv_bfloat16* __restrict__ Alo,
    const __nv_bfloat16* __restrict__ Bhi, const __nv_bfloat16* __restrict__ Blo,
    float* __restrict__ C, int Ntot)
{
    extern __shared__ char gsm[];
    const int tid  = threadIdx.x;
    const int wid  = tid >> 5, lane = tid & 31;
    const int cN   = blockIdx.x, cM = blockIdx.y;
    const int wm   = (wid & 3) * 32;
    const int wn   = (wid >> 2) * 64;

    const __nv_bfloat16* gAh = Ahi + (size_t)cM * 128 * GK;
    const __nv_bfloat16* gAl = Alo + (size_t)cM * 128 * GK;
    const __nv_bfloat16* gBh = Bhi + (size_t)cN * 128 * GK;
    const __nv_bfloat16* gBl = Blo + (size_t)cN * 128 * GK;

    const uint32_t smbase = smem_u32(gsm);

    float acc[2][8][4];
    #pragma unroll
    for (int mi = 0; mi < 2; mi++)
        #pragma unroll
        for (int nf = 0; nf < 8; nf++)
            #pragma unroll
            for (int e = 0; e < 4; e++) acc[mi][nf][e] = 0.f;

    const int aRow = wm + (lane & 15);
    const int aKof = (lane >> 4) * 16;
    const int bRow = wn + ((lane >> 4) << 3) + (lane & 7);
    const int bKof = ((lane >> 3) & 1) * 16;

    {
        uint32_t st = smbase;
        tile_loads(st + 0 * TILE_B, gAh, 0, tid);
        tile_loads(st + 1 * TILE_B, gAl, 0, tid);
        tile_loads(st + 2 * TILE_B, gBh, 0, tid);
        tile_loads(st + 3 * TILE_B, gBl, 0, tid);
        CP_COMMIT();
    }

    for (int kc = 0; kc < NSTEPS; kc++) {
        if (kc + 1 < NSTEPS) {
            uint32_t st = smbase + ((kc + 1) & 1) * STAGE_B;
            int k0 = (kc + 1) * KC;
            tile_loads(st + 0 * TILE_B, gAh, k0, tid);
            tile_loads(st + 1 * TILE_B, gAl, k0, tid);
            tile_loads(st + 2 * TILE_B, gBh, k0, tid);
            tile_loads(st + 3 * TILE_B, gBl, k0, tid);
            CP_COMMIT();
            CP_WAIT(1);
        } else {
            CP_WAIT(0);
        }
        __syncthreads();

        const uint32_t sAh = smbase + (kc & 1) * STAGE_B;
        const uint32_t sAl = sAh + TILE_B;
        const uint32_t sBh = sAh + 2 * TILE_B;
        const uint32_t sBl = sAh + 3 * TILE_B;

        #pragma unroll
        for (int kk = 0; kk < 4; kk++) {
            const int kb = kk * 32;
            uint32_t aH[2][4], aL[2][4], bH[4][4], bL[4][4];
            #pragma unroll
            for (int mi = 0; mi < 2; mi++) {
                uint32_t off = SWZ128((aRow + mi * 16) * 128 + kb + aKof);
                ldsm_x4(aH[mi], sAh + off);
                ldsm_x4(aL[mi], sAl + off);
            }
            #pragma unroll
            for (int g = 0; g < 4; g++) {
                uint32_t off = SWZ128((bRow + g * 16) * 128 + kb + bKof);
                ldsm_x4(bH[g], sBh + off);
                ldsm_x4(bL[g], sBl + off);
            }
            #pragma unroll
            for (int mi = 0; mi < 2; mi++)
                #pragma unroll
                for (int nf = 0; nf < 8; nf++) {
                    const uint32_t* bh = &bH[nf >> 1][(nf & 1) * 2];
                    const uint32_t* bl = &bL[nf >> 1][(nf & 1) * 2];
                    mma_bf16(acc[mi][nf], aH[mi], bh);
                    mma_bf16(acc[mi][nf], aH[mi], bl);
                    mma_bf16(acc[mi][nf], aL[mi], bh);
                }
        }
        __syncthreads();
    }

    const int row0 = cM * 128 + wm + (lane >> 2);
    const int col0 = cN * 128 + wn + (lane & 3) * 2;
    #pragma unroll
    for (int mi = 0; mi < 2; mi++)
        #pragma unroll
        for (int nf = 0; nf < 8; nf++) {
            int r = row0 + mi * 16;
            int c = col0 + nf * 8;
            if (MODE == 0) {
                float* c0 = C + (size_t)r * Ntot + c;
                float* c1 = c0 + 8 * Ntot;
                *(float2*)c0 = make_float2(acc[mi][nf][0], acc[mi][nf][1]);
                *(float2*)c1 = make_float2(acc[mi][nf][2], acc[mi][nf][3]);
            } else {
                write_qkv_pair(r,     c, acc[mi][nf][0], acc[mi][nf][1]);
                write_qkv_pair(r + 8, c, acc[mi][nf][2], acc[mi][nf][3]);
            }
        }
}

__global__ __launch_bounds__(256, 1) void qkv_gemm2_kernel() {
    gemm_body<1>(g_xhi, g_xlo, g_wqkvT_hi, g_wqkvT_lo, nullptr, QKV_N);
}
__global__ __launch_bounds__(256, 1) void out_gemm2_kernel(float* __restrict__ out) {
    gemm_body<0>(g_atthi, g_attlo, g_woutT_hi, g_woutT_lo, out, D_MODEL);
}

// ---------------------------------------------------------------------------
// Tensor-core causal flash attention (FA2-style), split-bf16 S and PV.
// CTA: 128 thr = 4 warps, 64 q rows (16/warp), BK=64 keys/iter, 2-stage KV.
// ---------------------------------------------------------------------------
#define AQ     64
#define AK     64
#define ATILE  8192                 // 64 rows x 128B
#define AQT    (SEQ / AQ)           // 32

__device__ __forceinline__ void load_tile64(
    uint32_t sbase, const __nv_bfloat16* __restrict__ g, int tid)
{
    #pragma unroll
    for (int j = 0; j < 4; j++) {
        int i = tid + j * 128;
        int r = i >> 3, c = i & 7;
        cp16(sbase + SWZ128(r * 128 + c * 16), g + (size_t)r * D_HEAD + c * 8);
    }
}

__global__ __launch_bounds__(128) void attn_tc_kernel()
{
    extern __shared__ char s_raw[];
    const int tid  = threadIdx.x;
    const int lane = tid & 31, wid = tid >> 5;
    const int qt = (AQT - 1) - blockIdx.x;   // long CTAs first
    const int hb = blockIdx.y;
    const int q0 = qt * AQ;
    const int wm = wid * 16;

    const uint32_t sb  = smem_u32(s_raw);
    const uint32_t sQh = sb, sQl = sb + ATILE;
    const uint32_t sKV = sb + 2 * ATILE;     // 2 stages x {Khi,Klo,Vhi,Vlo}

    const size_t headBase = (size_t)hb * SEQ * D_HEAD;
    const __nv_bfloat16* qh = g_qhi + headBase + (size_t)q0 * D_HEAD;
    const __nv_bfloat16* ql = g_qlo + headBase + (size_t)q0 * D_HEAD;

    // Prologue: Q (group 0), stage0 K/V (group 1)
    load_tile64(sQh, qh, tid);
    load_tile64(sQl, ql, tid);
    CP_COMMIT();
    {
        uint32_t st = sKV;
        load_tile64(st + 0 * ATILE, g_khi + headBase, tid);
        load_tile64(st + 1 * ATILE, g_klo + headBase, tid);
        load_tile64(st + 2 * ATILE, g_vhi + headBase, tid);
        load_tile64(st + 3 * ATILE, g_vlo + headBase, tid);
        CP_COMMIT();
    }
    CP_WAIT(1);          // Q ready
    __syncthreads();

    // Q fragments (held in regs for whole CTA)
    const int aRow = wm + (lane & 15);
    const int aKof = (lane >> 4) * 16;
    uint32_t Qh[4][4], Ql[4][4];
    #pragma unroll
    for (int kk = 0; kk < 4; kk++) {
        uint32_t off = SWZ128(aRow * 128 + kk * 32 + aKof);
        ldsm_x4(Qh[kk], sQh + off);
        ldsm_x4(Ql[kk], sQl + off);
    }

    const int bRow = ((lane >> 4) << 3) + (lane & 7);
    const int bKof = ((lane >> 3) & 1) * 16;
    const int vRow = lane & 15;
    const int vKof = (lane >> 4) * 16;

    float O[8][4];
    #pragma unroll
    for (int nd = 0; nd < 8; nd++)
        #pragma unroll
        for (int e = 0; e < 4; e++) O[nd][e] = 0.f;
    float m0 = -1e30f, m1 = -1e30f, l0 = 0.f, l1 = 0.f;

    const int qg0 = q0 + wm + (lane >> 2);
    const int qg1 = qg0 + 8;

    for (int kb = 0; kb <= q0; kb += AK) {
        const int stage = (kb >> 6) & 1;
        if (kb + AK <= q0) {
            uint32_t st = sKV + (stage ^ 1) * 4 * ATILE;
            size_t nb = headBase + (size_t)(kb + AK) * D_HEAD;
            load_tile64(st + 0 * ATILE, g_khi + nb, tid);
            load_tile64(st + 1 * ATILE, g_klo + nb, tid);
            load_tile64(st + 2 * ATILE, g_vhi + nb, tid);
            load_tile64(st + 3 * ATILE, g_vlo + nb, tid);
            CP_COMMIT();
            CP_WAIT(1);
        } else {
            CP_WAIT(0);
        }
        __syncthreads();

        const uint32_t sKh = sKV + stage * 4 * ATILE;
        const uint32_t sKl = sKh + ATILE;
        const uint32_t sVh = sKh + 2 * ATILE;
        const uint32_t sVl = sKh + 3 * ATILE;

        // ---- S = Q K^T (3-term split) ----
        float S[8][4];
        #pragma unroll
        for (int nf = 0; nf < 8; nf++)
            #pragma unroll
            for (int e = 0; e < 4; e++) S[nf][e] = 0.f;

        #pragma unroll
        for (int kk = 0; kk < 4; kk++) {
            uint32_t Kh[4][4], Kl[4][4];
            #pragma unroll
            for (int g = 0; g < 4; g++) {
                uint32_t off = SWZ128((bRow + g * 16) * 128 + kk * 32 + bKof);
                ldsm_x4(Kh[g], sKh + off);
                ldsm_x4(Kl[g], sKl + off);
            }
            #pragma unroll
            for (int nf = 0; nf < 8; nf++) {
                const uint32_t* bh = &Kh[nf >> 1][(nf & 1) * 2];
                const uint32_t* bl = &Kl[nf >> 1][(nf & 1) * 2];
                mma_bf16(S[nf], Qh[kk], bh);
                mma_bf16(S[nf], Qh[kk], bl);
                mma_bf16(S[nf], Ql[kk], bh);
            }
        }

        // ---- causal mask on diagonal tile ----
        if (kb == q0) {
            #pragma unroll
            for (int nf = 0; nf < 8; nf++) {
                int kg = kb + nf * 8 + (lane & 3) * 2;
                if (kg     > qg0) S[nf][0] = -1e30f;
                if (kg + 1 > qg0) S[nf][1] = -1e30f;
                if (kg     > qg1) S[nf][2] = -1e30f;
                if (kg + 1 > qg1) S[nf][3] = -1e30f;
            }
        }

        // ---- online softmax ----
        float rm0 = -1e30f, rm1 = -1e30f;
        #pragma unroll
        for (int nf = 0; nf < 8; nf++) {
            rm0 = fmaxf(rm0, fmaxf(S[nf][0], S[nf][1]));
            rm1 = fmaxf(rm1, fmaxf(S[nf][2], S[nf][3]));
        }
        rm0 = fmaxf(rm0, __shfl_xor_sync(0xffffffff, rm0, 1));
        rm0 = fmaxf(rm0, __shfl_xor_sync(0xffffffff, rm0, 2));
        rm1 = fmaxf(rm1, __shfl_xor_sync(0xffffffff, rm1, 1));
        rm1 = fmaxf(rm1, __shfl_xor_sync(0xffffffff, rm1, 2));

        float mn0 = fmaxf(m0, rm0), mn1 = fmaxf(m1, rm1);
        float c0 = __expf(m0 - mn0), c1 = __expf(m1 - mn1);
        m0 = mn0; m1 = mn1;

        float rs0 = 0.f, rs1 = 0.f;
        #pragma unroll
        for (int nf = 0; nf < 8; nf++) {
            S[nf][0] = __expf(S[nf][0] - m0);
            S[nf][1] = __expf(S[nf][1] - m0);
            S[nf][2] = __expf(S[nf][2] - m1);
            S[nf][3] = __expf(S[nf][3] - m1);
            rs0 += S[nf][0] + S[nf][1];
            rs1 += S[nf][2] + S[nf][3];
        }
        rs0 += __shfl_xor_sync(0xffffffff, rs0, 1);
        rs0 += __shfl_xor_sync(0xffffffff, rs0, 2);
        rs1 += __shfl_xor_sync(0xffffffff, rs1, 1);
        rs1 += __shfl_xor_sync(0xffffffff, rs1, 2);
        l0 = l0 * c0 + rs0;
        l1 = l1 * c1 + rs1;

        #pragma unroll
        for (int nd = 0; nd < 8; nd++) {
            O[nd][0] *= c0; O[nd][1] *= c0;
            O[nd][2] *= c1; O[nd][3] *= c1;
        }

        // ---- O += P V (3-term split, V^T via trans ldmatrix) ----
        #pragma unroll
        for (int kk = 0; kk < 4; kk++) {
            uint32_t Vh[4][4], Vl[4][4];
            #pragma unroll
            for (int gd = 0; gd < 4; gd++) {
                uint32_t off = SWZ128((kk * 16 + vRow) * 128 + gd * 32 + vKof);
                ldsm_x4t(Vh[gd], sVh + off);
                ldsm_x4t(Vl[gd], sVl + off);
            }
            const float* p0 = S[2 * kk];
            const float* p1 = S[2 * kk + 1];
            uint32_t ah[4], al[4];
            {
                __nv_bfloat16 h00 = __float2bfloat16(p0[0]), h01 = __float2bfloat16(p0[1]);
                __nv_bfloat16 h02 = __float2bfloat16(p0[2]), h03 = __float2bfloat16(p0[3]);
                __nv_bfloat16 h10 = __float2bfloat16(p1[0]), h11 = __float2bfloat16(p1[1]);
                __nv_bfloat16 h12 = __float2bfloat16(p1[2]), h13 = __float2bfloat16(p1[3]);
                ah[0] = pack_bf2(h00, h01);
                ah[1] = pack_bf2(h02, h03);
                ah[2] = pack_bf2(h10, h11);
                ah[3] = pack_bf2(h12, h13);
                al[0] = pack_bf2(__float2bfloat16(p0[0] - __bfloat162float(h00)),
                                 __float2bfloat16(p0[1] - __bfloat162float(h01)));
                al[1] = pack_bf2(__float2bfloat16(p0[2] - __bfloat162float(h02)),
                                 __float2bfloat16(p0[3] - __bfloat162float(h03)));
                al[2] = pack_bf2(__float2bfloat16(p1[0] - __bfloat162float(h10)),
                                 __float2bfloat16(p1[1] - __bfloat162float(h11)));
                al[3] = pack_bf2(__float2bfloat16(p1[2] - __bfloat162float(h12)),
                                 __float2bfloat16(p1[3] - __bfloat162float(h13)));
            }
            #pragma unroll
            for (int nd = 0; nd < 8; nd++) {
                const uint32_t* bh = &Vh[nd >> 1][(nd & 1) * 2];
                const uint32_t* bl = &Vl[nd >> 1][(nd & 1) * 2];
                mma_bf16(O[nd], ah, bh);
                mma_bf16(O[nd], ah, bl);
                mma_bf16(O[nd], al, bh);
            }
        }
        __syncthreads();
    }

    // ---- epilogue: normalize, split-write attn output [token][h*64+d] ----
    const float inv0 = 1.f / l0, inv1 = 1.f / l1;
    const int b = hb >> 4, h = hb & 15;
    const size_t base0 = ((size_t)(b * SEQ + qg0)) * D_MODEL + h * D_HEAD;
    const size_t base1 = ((size_t)(b * SEQ + qg1)) * D_MODEL + h * D_HEAD;
    #pragma unroll
    for (int nd = 0; nd < 8; nd++) {
        int d = nd * 8 + (lane & 3) * 2;
        float v0 = O[nd][0] * inv0, v1 = O[nd][1] * inv0;
        float v2 = O[nd][2] * inv1, v3 = O[nd][3] * inv1;
        __nv_bfloat16 h0 = __float2bfloat16(v0), h1 = __float2bfloat16(v1);
        __nv_bfloat16 h2 = __float2bfloat16(v2), h3 = __float2bfloat16(v3);
        *(uint32_t*)&g_atthi[base0 + d] = pack_bf2(h0, h1);
        *(uint32_t*)&g_attlo[base0 + d] =
            pack_bf2(__float2bfloat16(v0 - __bfloat162float(h0)),
                     __float2bfloat16(v1 - __bfloat162float(h1)));
        *(uint32_t*)&g_atthi[base1 + d] = pack_bf2(h2, h3);
        *(uint32_t*)&g_attlo[base1 + d] =
            pack_bf2(__float2bfloat16(v2 - __bfloat162float(h2)),
                     __float2bfloat16(v3 - __bfloat162float(h3)));
    }
}

// ---------------------------------------------------------------------------
extern "C" void kernel_launch(void* const* d_in, const int* in_sizes, int n_in,
                              void* d_out, int out_size)
{
    const float* x     = (const float*)d_in[0];
    const float* W_qkv = (const float*)d_in[1];
    const float* W_out = (const float*)d_in[2];
    float* out = (float*)d_out;

    const int gemm_smem = 2 * STAGE_B;                 // 128 KB
    const int attn_smem = 2 * ATILE + 2 * 4 * ATILE;   // 80 KB
    cudaFuncSetAttribute(qkv_gemm2_kernel,
                         cudaFuncAttributeMaxDynamicSharedMemorySize, gemm_smem);
    cudaFuncSetAttribute(out_gemm2_kernel,
                         cudaFuncAttributeMaxDynamicSharedMemorySize, gemm_smem);
    cudaFuncSetAttribute(attn_tc_kernel,
                         cudaFuncAttributeMaxDynamicSharedMemorySize, attn_smem);

    // 0) Input split / weight transposes
    {
        size_t n4 = (size_t)M_TOK * D_MODEL / 4;
        split_x_kernel<<<(unsigned)((n4 + 255) / 256), 256>>>(x);
        dim3 blk(32, 8);
        tr_wqkv_kernel<<<dim3(QKV_N / 32, D_MODEL / 32), blk>>>(W_qkv);
        tr_wout_kernel<<<dim3(D_MODEL / 32, D_MODEL / 32), blk>>>(W_out);
    }
    // 1) QKV projection -> split q/k/v (head-contiguous, q pre-scaled)
    qkv_gemm2_kernel<<<dim3(QKV_N / 128, M_TOK / 128), 256, gemm_smem>>>();
    // 2) Tensor-core causal flash attention -> g_att{hi,lo}
    attn_tc_kernel<<<dim3(AQT, HB), 128, attn_smem>>>();
    // 3) Output projection -> out (fp32)
    out_gemm2_kernel<<<dim3(D_MODEL / 128, M_TOK / 128), 256, gemm_smem>>>(out);
}

// round 6
// speedup vs baseline: 4.4535x; 1.0684x over previous
#include <cuda_runtime.h>
#include <cuda_bf16.h>
#include <math.h>
#include <stdint.h>

#define D_MODEL 1024
#define N_HEADS 16
#define D_HEAD  64
#define BATCH   4
#define SEQ     2048
#define M_TOK   (BATCH * SEQ)     // 8192
#define QKV_N   (3 * D_MODEL)     // 3072
#define GK      1024
#define HB      (BATCH * N_HEADS) // 64

// ---------------------------------------------------------------------------
// Device-global scratch
// ---------------------------------------------------------------------------
__device__ __nv_bfloat16 g_xhi[(size_t)M_TOK * D_MODEL];
__device__ __nv_bfloat16 g_xlo[(size_t)M_TOK * D_MODEL];
__device__ __nv_bfloat16 g_wqkvT_hi[(size_t)QKV_N * D_MODEL];
__device__ __nv_bfloat16 g_wqkvT_lo[(size_t)QKV_N * D_MODEL];
__device__ __nv_bfloat16 g_woutT_hi[(size_t)D_MODEL * D_MODEL];
__device__ __nv_bfloat16 g_woutT_lo[(size_t)D_MODEL * D_MODEL];
// q/k/v split, head-contiguous: [(b*16+h)][t][64]
__device__ __nv_bfloat16 g_qhi[(size_t)HB * SEQ * D_HEAD];
__device__ __nv_bfloat16 g_qlo[(size_t)HB * SEQ * D_HEAD];
__device__ __nv_bfloat16 g_khi[(size_t)HB * SEQ * D_HEAD];
__device__ __nv_bfloat16 g_klo[(size_t)HB * SEQ * D_HEAD];
__device__ __nv_bfloat16 g_vhi[(size_t)HB * SEQ * D_HEAD];
__device__ __nv_bfloat16 g_vlo[(size_t)HB * SEQ * D_HEAD];
__device__ __nv_bfloat16 g_atthi[(size_t)M_TOK * D_MODEL];
__device__ __nv_bfloat16 g_attlo[(size_t)M_TOK * D_MODEL];

// ---------------------------------------------------------------------------
// Baseline-PTX helpers (compute_103 target: no tcgen05)
// ---------------------------------------------------------------------------
__device__ __forceinline__ uint32_t smem_u32(const void* p) {
    uint32_t a;
    asm("{ .reg .u64 t; cvta.to.shared.u64 t, %1; cvt.u32.u64 %0, t; }"
        : "=r"(a) : "l"(p));
    return a;
}
__device__ __forceinline__ void cp16(uint32_t dst, const void* src) {
    asm volatile("cp.async.cg.shared.global [%0], [%1], 16;"
                 :: "r"(dst), "l"(src) : "memory");
}
#define CP_COMMIT() asm volatile("cp.async.commit_group;" ::: "memory")
#define CP_WAIT(n)  asm volatile("cp.async.wait_group %0;" :: "n"(n) : "memory")

__device__ __forceinline__ void ldsm_x4(uint32_t* r, uint32_t addr) {
    asm volatile("ldmatrix.sync.aligned.m8n8.x4.shared.b16 {%0,%1,%2,%3}, [%4];"
                 : "=r"(r[0]), "=r"(r[1]), "=r"(r[2]), "=r"(r[3]) : "r"(addr));
}
__device__ __forceinline__ void ldsm_x4t(uint32_t* r, uint32_t addr) {
    asm volatile("ldmatrix.sync.aligned.m8n8.x4.trans.shared.b16 {%0,%1,%2,%3}, [%4];"
                 : "=r"(r[0]), "=r"(r[1]), "=r"(r[2]), "=r"(r[3]) : "r"(addr));
}
__device__ __forceinline__ void mma_bf16(float* d, const uint32_t* a, const uint32_t* b) {
    asm volatile(
        "mma.sync.aligned.m16n8k16.row.col.f32.bf16.bf16.f32 "
        "{%0,%1,%2,%3}, {%4,%5,%6,%7}, {%8,%9}, {%0,%1,%2,%3};"
        : "+f"(d[0]), "+f"(d[1]), "+f"(d[2]), "+f"(d[3])
        : "r"(a[0]), "r"(a[1]), "r"(a[2]), "r"(a[3]), "r"(b[0]), "r"(b[1]));
}
#define SWZ128(o) ((o) ^ (((o) >> 3) & 0x70))
#define SWZ64(o)  ((o) ^ (((o) >> 3) & 0x30))

__device__ __forceinline__ uint32_t pack_bf2(__nv_bfloat16 a, __nv_bfloat16 b) {
    __nv_bfloat162 t(a, b);
    return *(uint32_t*)&t;
}

// ---------------------------------------------------------------------------
// Prep kernels
// ---------------------------------------------------------------------------
__global__ void split_x_kernel(const float* __restrict__ x) {
    size_t i = ((size_t)blockIdx.x * blockDim.x + threadIdx.x) * 4;
    if (i >= (size_t)M_TOK * D_MODEL) return;
    float4 v = *(const float4*)(x + i);
    __nv_bfloat16 h0 = __float2bfloat16(v.x), h1 = __float2bfloat16(v.y);
    __nv_bfloat16 h2 = __float2bfloat16(v.z), h3 = __float2bfloat16(v.w);
    __nv_bfloat162* hp = (__nv_bfloat162*)(g_xhi + i);
    __nv_bfloat162* lp = (__nv_bfloat162*)(g_xlo + i);
    hp[0] = __nv_bfloat162(h0, h1);
    hp[1] = __nv_bfloat162(h2, h3);
    lp[0] = __nv_bfloat162(__float2bfloat16(v.x - __bfloat162float(h0)),
                           __float2bfloat16(v.y - __bfloat162float(h1)));
    lp[1] = __nv_bfloat162(__float2bfloat16(v.z - __bfloat162float(h2)),
                           __float2bfloat16(v.w - __bfloat162float(h3)));
}

__device__ __forceinline__ void transpose_split_body(
    const float* __restrict__ W, __nv_bfloat16* __restrict__ Thi,
    __nv_bfloat16* __restrict__ Tlo, int K, int N)
{
    __shared__ float t[32][33];
    int tx = threadIdx.x, ty = threadIdx.y;
    int x = blockIdx.x * 32 + tx;
    int y0 = blockIdx.y * 32;
    #pragma unroll
    for (int j = 0; j < 32; j += 8)
        t[ty + j][tx] = W[(size_t)(y0 + ty + j) * N + x];
    __syncthreads();
    int xo = y0 + tx;
    int yo = blockIdx.x * 32;
    #pragma unroll
    for (int j = 0; j < 32; j += 8) {
        float v = t[tx][ty + j];
        __nv_bfloat16 h = __float2bfloat16(v);
        size_t o = (size_t)(yo + ty + j) * K + xo;
        Thi[o] = h;
        Tlo[o] = __float2bfloat16(v - __bfloat162float(h));
    }
}
__global__ void tr_wqkv_kernel(const float* __restrict__ W) {
    transpose_split_body(W, g_wqkvT_hi, g_wqkvT_lo, D_MODEL, QKV_N);
}
__global__ void tr_wout_kernel(const float* __restrict__ W) {
    transpose_split_body(W, g_woutT_hi, g_woutT_lo, D_MODEL, D_MODEL);
}

// ---------------------------------------------------------------------------
// GEMM v3: CTA 128x128, 4 warps (64x64 warp tile), KC=32 (SW64 rows),
// 3-stage cp.async ring, 2 CTAs/SM. 3-term split-bf16 mma.
// MODE 0: fp32 C. MODE 1: split-write q/k/v head-contiguous.
// ---------------------------------------------------------------------------
#define KC       32
#define TILE_B3  (128 * 64)          // 8KB: 128 rows x 64B
#define STAGE_B3 (4 * TILE_B3)       // 32KB: Ahi,Alo,Bhi,Blo
#define NSTEPS3  (GK / KC)           // 32

__device__ __forceinline__ void tile_loads3(
    uint32_t sbase, const __nv_bfloat16* __restrict__ g, int k0, int tid)
{
    #pragma unroll
    for (int j = 0; j < 4; j++) {
        int i = tid + j * 128;            // 0..511 chunk id (16B chunks)
        int r = i >> 2, c = i & 3;
        cp16(sbase + SWZ64(r * 64 + c * 16), g + (size_t)r * GK + k0 + c * 8);
    }
}

__device__ __forceinline__ void stage_loads3(
    uint32_t st,
    const __nv_bfloat16* gAh, const __nv_bfloat16* gAl,
    const __nv_bfloat16* gBh, const __nv_bfloat16* gBl, int k0, int tid)
{
    tile_loads3(st + 0 * TILE_B3, gAh, k0, tid);
    tile_loads3(st + 1 * TILE_B3, gAl, k0, tid);
    tile_loads3(st + 2 * TILE_B3, gBh, k0, tid);
    tile_loads3(st + 3 * TILE_B3, gBl, k0, tid);
}

__device__ __forceinline__ void write_qkv_pair(int row, int col, float v0, float v1) {
    int b = row >> 11, t = row & 2047;
    int which = col >> 10;
    int h = (col >> 6) & 15;
    int d = col & 63;
    if (which == 0) { v0 *= 0.125f; v1 *= 0.125f; }   // fold 1/sqrt(64) into q
    size_t off = (((size_t)((b << 4) + h) << 11) + (size_t)t) * D_HEAD + d;
    __nv_bfloat16 h0 = __float2bfloat16(v0), h1 = __float2bfloat16(v1);
    uint32_t hi = pack_bf2(h0, h1);
    uint32_t lo = pack_bf2(__float2bfloat16(v0 - __bfloat162float(h0)),
                           __float2bfloat16(v1 - __bfloat162float(h1)));
    __nv_bfloat16* dh = (which == 0) ? g_qhi : (which == 1) ? g_khi : g_vhi;
    __nv_bfloat16* dl = (which == 0) ? g_qlo : (which == 1) ? g_klo : g_vlo;
    *(uint32_t*)&dh[off] = hi;
    *(uint32_t*)&dl[off] = lo;
}

template <int MODE>
__device__ __forceinline__ void gemm_body(
    const __nv_bfloat16* __restrict__ Ahi, const __nv_bfloat16* __restrict__ Alo,
    const __nv_bfloat16* __restrict__ Bhi, const __nv_bfloat16* __restrict__ Blo,
    float* __restrict__ C, int Ntot)
{
    extern __shared__ char gsm[];
    const int tid  = threadIdx.x;
    const int wid  = tid >> 5, lane = tid & 31;
    const int cN   = blockIdx.x, cM = blockIdx.y;
    const int wm   = (wid & 1) * 64;
    const int wn   = (wid >> 1) * 64;

    const __nv_bfloat16* gAh = Ahi + (size_t)cM * 128 * GK;
    const __nv_bfloat16* gAl = Alo + (size_t)cM * 128 * GK;
    const __nv_bfloat16* gBh = Bhi + (size_t)cN * 128 * GK;
    const __nv_bfloat16* gBl = Blo + (size_t)cN * 128 * GK;

    const uint32_t smbase = smem_u32(gsm);

    float acc[4][8][4];
    #pragma unroll
    for (int mi = 0; mi < 4; mi++)
        #pragma unroll
        for (int nf = 0; nf < 8; nf++)
            #pragma unroll
            for (int e = 0; e < 4; e++) acc[mi][nf][e] = 0.f;

    const int aRow = wm + (lane & 15);
    const int aKof = (lane >> 4) * 16;
    const int bRow = wn + ((lane >> 4) << 3) + (lane & 7);
    const int bKof = ((lane >> 3) & 1) * 16;

    // prologue: stages 0,1
    stage_loads3(smbase,            gAh, gAl, gBh, gBl, 0, tid);
    CP_COMMIT();
    stage_loads3(smbase + STAGE_B3, gAh, gAl, gBh, gBl, KC, tid);
    CP_COMMIT();

    for (int kc = 0; kc < NSTEPS3; kc++) {
        const int slot = kc % 3;
        if (kc + 2 < NSTEPS3) {
            stage_loads3(smbase + ((kc + 2) % 3) * STAGE_B3,
                         gAh, gAl, gBh, gBl, (kc + 2) * KC, tid);
            CP_COMMIT();
            CP_WAIT(2);
        } else if (kc + 1 < NSTEPS3) {
            CP_WAIT(1);
        } else {
            CP_WAIT(0);
        }
        __syncthreads();

        const uint32_t sAh = smbase + slot * STAGE_B3;
        const uint32_t sAl = sAh + TILE_B3;
        const uint32_t sBh = sAh + 2 * TILE_B3;
        const uint32_t sBl = sAh + 3 * TILE_B3;

        #pragma unroll
        for (int kk = 0; kk < 2; kk++) {          // 2 x k16 within KC=32
            const int kb = kk * 32;
            uint32_t aH[4][4], aL[4][4], bH[4][4], bL[4][4];
            #pragma unroll
            for (int mi = 0; mi < 4; mi++) {
                uint32_t off = SWZ64((aRow + mi * 16) * 64 + kb + aKof);
                ldsm_x4(aH[mi], sAh + off);
                ldsm_x4(aL[mi], sAl + off);
            }
            #pragma unroll
            for (int g = 0; g < 4; g++) {
                uint32_t off = SWZ64((bRow + g * 16) * 64 + kb + bKof);
                ldsm_x4(bH[g], sBh + off);
                ldsm_x4(bL[g], sBl + off);
            }
            #pragma unroll
            for (int mi = 0; mi < 4; mi++)
                #pragma unroll
                for (int nf = 0; nf < 8; nf++) {
                    const uint32_t* bh = &bH[nf >> 1][(nf & 1) * 2];
                    const uint32_t* bl = &bL[nf >> 1][(nf & 1) * 2];
                    mma_bf16(acc[mi][nf], aH[mi], bh);
                    mma_bf16(acc[mi][nf], aH[mi], bl);
                    mma_bf16(acc[mi][nf], aL[mi], bh);
                }
        }
        __syncthreads();
    }

    const int row0 = cM * 128 + wm + (lane >> 2);
    const int col0 = cN * 128 + wn + (lane & 3) * 2;
    #pragma unroll
    for (int mi = 0; mi < 4; mi++)
        #pragma unroll
        for (int nf = 0; nf < 8; nf++) {
            int r = row0 + mi * 16;
            int c = col0 + nf * 8;
            if (MODE == 0) {
                float* c0 = C + (size_t)r * Ntot + c;
                float* c1 = c0 + 8 * Ntot;
                *(float2*)c0 = make_float2(acc[mi][nf][0], acc[mi][nf][1]);
                *(float2*)c1 = make_float2(acc[mi][nf][2], acc[mi][nf][3]);
            } else {
                write_qkv_pair(r,     c, acc[mi][nf][0], acc[mi][nf][1]);
                write_qkv_pair(r + 8, c, acc[mi][nf][2], acc[mi][nf][3]);
            }
        }
}

__global__ __launch_bounds__(128, 2) void qkv_gemm2_kernel() {
    gemm_body<1>(g_xhi, g_xlo, g_wqkvT_hi, g_wqkvT_lo, nullptr, QKV_N);
}
__global__ __launch_bounds__(128, 2) void out_gemm2_kernel(float* __restrict__ out) {
    gemm_body<0>(g_atthi, g_attlo, g_woutT_hi, g_woutT_lo, out, D_MODEL);
}

// ---------------------------------------------------------------------------
// Tensor-core causal flash attention (FA2-style), split-bf16 S and PV.
// CTA: 128 thr = 4 warps, 64 q rows (16/warp), BK=64 keys/iter, 2-stage KV.
// ---------------------------------------------------------------------------
#define AQ     64
#define AK     64
#define ATILE  8192                 // 64 rows x 128B
#define AQT    (SEQ / AQ)           // 32

__device__ __forceinline__ void load_tile64(
    uint32_t sbase, const __nv_bfloat16* __restrict__ g, int tid)
{
    #pragma unroll
    for (int j = 0; j < 4; j++) {
        int i = tid + j * 128;
        int r = i >> 3, c = i & 7;
        cp16(sbase + SWZ128(r * 128 + c * 16), g + (size_t)r * D_HEAD + c * 8);
    }
}

__global__ __launch_bounds__(128) void attn_tc_kernel()
{
    extern __shared__ char s_raw[];
    const int tid  = threadIdx.x;
    const int lane = tid & 31, wid = tid >> 5;
    const int qt = (AQT - 1) - blockIdx.x;   // long CTAs first
    const int hb = blockIdx.y;
    const int q0 = qt * AQ;
    const int wm = wid * 16;

    const uint32_t sb  = smem_u32(s_raw);
    const uint32_t sQh = sb, sQl = sb + ATILE;
    const uint32_t sKV = sb + 2 * ATILE;     // 2 stages x {Khi,Klo,Vhi,Vlo}

    const size_t headBase = (size_t)hb * SEQ * D_HEAD;
    const __nv_bfloat16* qh = g_qhi + headBase + (size_t)q0 * D_HEAD;
    const __nv_bfloat16* ql = g_qlo + headBase + (size_t)q0 * D_HEAD;

    load_tile64(sQh, qh, tid);
    load_tile64(sQl, ql, tid);
    CP_COMMIT();
    {
        uint32_t st = sKV;
        load_tile64(st + 0 * ATILE, g_khi + headBase, tid);
        load_tile64(st + 1 * ATILE, g_klo + headBase, tid);
        load_tile64(st + 2 * ATILE, g_vhi + headBase, tid);
        load_tile64(st + 3 * ATILE, g_vlo + headBase, tid);
        CP_COMMIT();
    }
    CP_WAIT(1);
    __syncthreads();

    const int aRow = wm + (lane & 15);
    const int aKof = (lane >> 4) * 16;
    uint32_t Qh[4][4], Ql[4][4];
    #pragma unroll
    for (int kk = 0; kk < 4; kk++) {
        uint32_t off = SWZ128(aRow * 128 + kk * 32 + aKof);
        ldsm_x4(Qh[kk], sQh + off);
        ldsm_x4(Ql[kk], sQl + off);
    }

    const int bRow = ((lane >> 4) << 3) + (lane & 7);
    const int bKof = ((lane >> 3) & 1) * 16;
    const int vRow = lane & 15;
    const int vKof = (lane >> 4) * 16;

    float O[8][4];
    #pragma unroll
    for (int nd = 0; nd < 8; nd++)
        #pragma unroll
        for (int e = 0; e < 4; e++) O[nd][e] = 0.f;
    float m0 = -1e30f, m1 = -1e30f, l0 = 0.f, l1 = 0.f;

    const int qg0 = q0 + wm + (lane >> 2);
    const int qg1 = qg0 + 8;

    for (int kb = 0; kb <= q0; kb += AK) {
        const int stage = (kb >> 6) & 1;
        if (kb + AK <= q0) {
            uint32_t st = sKV + (stage ^ 1) * 4 * ATILE;
            size_t nb = headBase + (size_t)(kb + AK) * D_HEAD;
            load_tile64(st + 0 * ATILE, g_khi + nb, tid);
            load_tile64(st + 1 * ATILE, g_klo + nb, tid);
            load_tile64(st + 2 * ATILE, g_vhi + nb, tid);
            load_tile64(st + 3 * ATILE, g_vlo + nb, tid);
            CP_COMMIT();
            CP_WAIT(1);
        } else {
            CP_WAIT(0);
        }
        __syncthreads();

        const uint32_t sKh = sKV + stage * 4 * ATILE;
        const uint32_t sKl = sKh + ATILE;
        const uint32_t sVh = sKh + 2 * ATILE;
        const uint32_t sVl = sKh + 3 * ATILE;

        float S[8][4];
        #pragma unroll
        for (int nf = 0; nf < 8; nf++)
            #pragma unroll
            for (int e = 0; e < 4; e++) S[nf][e] = 0.f;

        #pragma unroll
        for (int kk = 0; kk < 4; kk++) {
            uint32_t Kh[4][4], Kl[4][4];
            #pragma unroll
            for (int g = 0; g < 4; g++) {
                uint32_t off = SWZ128((bRow + g * 16) * 128 + kk * 32 + bKof);
                ldsm_x4(Kh[g], sKh + off);
                ldsm_x4(Kl[g], sKl + off);
            }
            #pragma unroll
            for (int nf = 0; nf < 8; nf++) {
                const uint32_t* bh = &Kh[nf >> 1][(nf & 1) * 2];
                const uint32_t* bl = &Kl[nf >> 1][(nf & 1) * 2];
                mma_bf16(S[nf], Qh[kk], bh);
                mma_bf16(S[nf], Qh[kk], bl);
                mma_bf16(S[nf], Ql[kk], bh);
            }
        }

        if (kb == q0) {
            #pragma unroll
            for (int nf = 0; nf < 8; nf++) {
                int kg = kb + nf * 8 + (lane & 3) * 2;
                if (kg     > qg0) S[nf][0] = -1e30f;
                if (kg + 1 > qg0) S[nf][1] = -1e30f;
                if (kg     > qg1) S[nf][2] = -1e30f;
                if (kg + 1 > qg1) S[nf][3] = -1e30f;
            }
        }

        float rm0 = -1e30f, rm1 = -1e30f;
        #pragma unroll
        for (int nf = 0; nf < 8; nf++) {
            rm0 = fmaxf(rm0, fmaxf(S[nf][0], S[nf][1]));
            rm1 = fmaxf(rm1, fmaxf(S[nf][2], S[nf][3]));
        }
        rm0 = fmaxf(rm0, __shfl_xor_sync(0xffffffff, rm0, 1));
        rm0 = fmaxf(rm0, __shfl_xor_sync(0xffffffff, rm0, 2));
        rm1 = fmaxf(rm1, __shfl_xor_sync(0xffffffff, rm1, 1));
        rm1 = fmaxf(rm1, __shfl_xor_sync(0xffffffff, rm1, 2));

        float mn0 = fmaxf(m0, rm0), mn1 = fmaxf(m1, rm1);
        float c0 = __expf(m0 - mn0), c1 = __expf(m1 - mn1);
        m0 = mn0; m1 = mn1;

        float rs0 = 0.f, rs1 = 0.f;
        #pragma unroll
        for (int nf = 0; nf < 8; nf++) {
            S[nf][0] = __expf(S[nf][0] - m0);
            S[nf][1] = __expf(S[nf][1] - m0);
            S[nf][2] = __expf(S[nf][2] - m1);
            S[nf][3] = __expf(S[nf][3] - m1);
            rs0 += S[nf][0] + S[nf][1];
            rs1 += S[nf][2] + S[nf][3];
        }
        rs0 += __shfl_xor_sync(0xffffffff, rs0, 1);
        rs0 += __shfl_xor_sync(0xffffffff, rs0, 2);
        rs1 += __shfl_xor_sync(0xffffffff, rs1, 1);
        rs1 += __shfl_xor_sync(0xffffffff, rs1, 2);
        l0 = l0 * c0 + rs0;
        l1 = l1 * c1 + rs1;

        #pragma unroll
        for (int nd = 0; nd < 8; nd++) {
            O[nd][0] *= c0; O[nd][1] *= c0;
            O[nd][2] *= c1; O[nd][3] *= c1;
        }

        #pragma unroll
        for (int kk = 0; kk < 4; kk++) {
            uint32_t Vh[4][4], Vl[4][4];
            #pragma unroll
            for (int gd = 0; gd < 4; gd++) {
                uint32_t off = SWZ128((kk * 16 + vRow) * 128 + gd * 32 + vKof);
                ldsm_x4t(Vh[gd], sVh + off);
                ldsm_x4t(Vl[gd], sVl + off);
            }
            const float* p0 = S[2 * kk];
            const float* p1 = S[2 * kk + 1];
            uint32_t ah[4], al[4];
            {
                __nv_bfloat16 h00 = __float2bfloat16(p0[0]), h01 = __float2bfloat16(p0[1]);
                __nv_bfloat16 h02 = __float2bfloat16(p0[2]), h03 = __float2bfloat16(p0[3]);
                __nv_bfloat16 h10 = __float2bfloat16(p1[0]), h11 = __float2bfloat16(p1[1]);
                __nv_bfloat16 h12 = __float2bfloat16(p1[2]), h13 = __float2bfloat16(p1[3]);
                ah[0] = pack_bf2(h00, h01);
                ah[1] = pack_bf2(h02, h03);
                ah[2] = pack_bf2(h10, h11);
                ah[3] = pack_bf2(h12, h13);
                al[0] = pack_bf2(__float2bfloat16(p0[0] - __bfloat162float(h00)),
                                 __float2bfloat16(p0[1] - __bfloat162float(h01)));
                al[1] = pack_bf2(__float2bfloat16(p0[2] - __bfloat162float(h02)),
                                 __float2bfloat16(p0[3] - __bfloat162float(h03)));
                al[2] = pack_bf2(__float2bfloat16(p1[0] - __bfloat162float(h10)),
                                 __float2bfloat16(p1[1] - __bfloat162float(h11)));
                al[3] = pack_bf2(__float2bfloat16(p1[2] - __bfloat162float(h12)),
                                 __float2bfloat16(p1[3] - __bfloat162float(h13)));
            }
            #pragma unroll
            for (int nd = 0; nd < 8; nd++) {
                const uint32_t* bh = &Vh[nd >> 1][(nd & 1) * 2];
                const uint32_t* bl = &Vl[nd >> 1][(nd & 1) * 2];
                mma_bf16(O[nd], ah, bh);
                mma_bf16(O[nd], ah, bl);
                mma_bf16(O[nd], al, bh);
            }
        }
        __syncthreads();
    }

    const float inv0 = 1.f / l0, inv1 = 1.f / l1;
    const int b = hb >> 4, h = hb & 15;
    const size_t base0 = ((size_t)(b * SEQ + qg0)) * D_MODEL + h * D_HEAD;
    const size_t base1 = ((size_t)(b * SEQ + qg1)) * D_MODEL + h * D_HEAD;
    #pragma unroll
    for (int nd = 0; nd < 8; nd++) {
        int d = nd * 8 + (lane & 3) * 2;
        float v0 = O[nd][0] * inv0, v1 = O[nd][1] * inv0;
        float v2 = O[nd][2] * inv1, v3 = O[nd][3] * inv1;
        __nv_bfloat16 h0 = __float2bfloat16(v0), h1 = __float2bfloat16(v1);
        __nv_bfloat16 h2 = __float2bfloat16(v2), h3 = __float2bfloat16(v3);
        *(uint32_t*)&g_atthi[base0 + d] = pack_bf2(h0, h1);
        *(uint32_t*)&g_attlo[base0 + d] =
            pack_bf2(__float2bfloat16(v0 - __bfloat162float(h0)),
                     __float2bfloat16(v1 - __bfloat162float(h1)));
        *(uint32_t*)&g_atthi[base1 + d] = pack_bf2(h2, h3);
        *(uint32_t*)&g_attlo[base1 + d] =
            pack_bf2(__float2bfloat16(v2 - __bfloat162float(h2)),
                     __float2bfloat16(v3 - __bfloat162float(h3)));
    }
}

// ---------------------------------------------------------------------------
extern "C" void kernel_launch(void* const* d_in, const int* in_sizes, int n_in,
                              void* d_out, int out_size)
{
    const float* x     = (const float*)d_in[0];
    const float* W_qkv = (const float*)d_in[1];
    const float* W_out = (const float*)d_in[2];
    float* out = (float*)d_out;

    const int gemm_smem = 3 * STAGE_B3;                // 96 KB
    const int attn_smem = 2 * ATILE + 2 * 4 * ATILE;   // 80 KB
    cudaFuncSetAttribute(qkv_gemm2_kernel,
                         cudaFuncAttributeMaxDynamicSharedMemorySize, gemm_smem);
    cudaFuncSetAttribute(out_gemm2_kernel,
                         cudaFuncAttributeMaxDynamicSharedMemorySize, gemm_smem);
    cudaFuncSetAttribute(attn_tc_kernel,
                         cudaFuncAttributeMaxDynamicSharedMemorySize, attn_smem);

    // 0) Input split / weight transposes
    {
        size_t n4 = (size_t)M_TOK * D_MODEL / 4;
        split_x_kernel<<<(unsigned)((n4 + 255) / 256), 256>>>(x);
        dim3 blk(32, 8);
        tr_wqkv_kernel<<<dim3(QKV_N / 32, D_MODEL / 32), blk>>>(W_qkv);
        tr_wout_kernel<<<dim3(D_MODEL / 32, D_MODEL / 32), blk>>>(W_out);
    }
    // 1) QKV projection -> split q/k/v (head-contiguous, q pre-scaled)
    qkv_gemm2_kernel<<<dim3(QKV_N / 128, M_TOK / 128), 128, gemm_smem>>>();
    // 2) Tensor-core causal flash attention -> g_att{hi,lo}
    attn_tc_kernel<<<dim3(AQT, HB), 128, attn_smem>>>();
    // 3) Output projection -> out (fp32)
    out_gemm2_kernel<<<dim3(D_MODEL / 128, M_TOK / 128), 128, gemm_smem>>>(out);
}